// round 1
// baseline (speedup 1.0000x reference)
#include <cuda_runtime.h>
#include <math.h>

// Problem dims
#define Bb 8
#define Ss 512
#define Ee 512
#define NH 8
#define HDm 64
#define ROWS (Bb*Ss)        // 4096 token rows
#define CLS_H 16000
#define VOC 8000
#define SQRT_E 22.627416997969522f
#define QK_SCALE 0.04419417382415922f   // 1/sqrt(512)
#define LN_EPS 1e-3f

// ---------------- scratch (device globals; no allocations allowed) -------------
__device__ float g_x[ROWS*Ee];
__device__ float g_y[ROWS*Ee];
__device__ float g_q[ROWS*Ee];
__device__ float g_k[ROWS*Ee];
__device__ float g_v[ROWS*Ee];
__device__ float g_att[ROWS*Ee];
__device__ float g_t0[ROWS*Ee];
__device__ float g_t1[ROWS*Ee];
__device__ float g_t2[ROWS*Ee];
__device__ float g_w[Ee*Ee];
__device__ float g_logits[Bb*NH*Ss*Ss];   // 16.77M floats
__device__ float g_hid[(size_t)ROWS*CLS_H]; // 65.5M floats (262MB)

// ---------------- embedding + positional encoding ----------------
__global__ __launch_bounds__(256) void embed_kernel(
    const int* __restrict__ ids, const float* __restrict__ emb, float* __restrict__ out)
{
    int bs = blockIdx.x;            // 0..4095
    int s  = bs & (Ss - 1);
    int id = ids[bs];
    const float* erow = emb + (size_t)id * Ee;
    float* orow = out + (size_t)bs * Ee;
    for (int e = threadIdx.x; e < Ee; e += blockDim.x) {
        int i = e & 255;
        // rate = 10000^{-(i/256)}
        float rate = expf(-(float)i * (9.210340371976184f / 256.0f));
        float ang = (float)s * rate;
        float p = (e < 256) ? sinf(ang) : cosf(ang);
        orow[e] = erow[e] * SQRT_E + p;
    }
}

// ---------------- repack [H,E,HD] -> [E, H*HD] row-major ----------------
__global__ __launch_bounds__(256) void repack_kernel(
    const float* __restrict__ w, float* __restrict__ out)
{
    int e = blockIdx.x;
    for (int j = threadIdx.x; j < Ee; j += blockDim.x) {
        out[e * Ee + j] = w[(j >> 6) * (Ee * HDm) + e * HDm + (j & 63)];
    }
}

// ---------------- tiled SGEMM: C[M,N] = A[M,K] @ B[K,N] (+bias, opt relu) ------
// M % 128 == 0, K % 16 == 0 assumed; N guarded.
__global__ __launch_bounds__(256) void sgemm_kernel(
    const float* __restrict__ A, const float* __restrict__ B,
    const float* __restrict__ bias, float* __restrict__ C,
    int M, int N, int K, int relu)
{
    __shared__ float As[16][128];
    __shared__ float Bs[16][128];

    const int t  = threadIdx.x;
    const int tx = t & 15;
    const int ty = t >> 4;
    const int row0 = blockIdx.y * 128;
    const int col0 = blockIdx.x * 128;

    // A loader: 64 rows x 4 float4 per pass, 2 passes
    const int aRow = t >> 2;          // 0..63
    const int aCol = (t & 3) * 4;     // 0,4,8,12
    // B loader: 8 rows x 32 float4 per pass, 2 passes
    const int bRow = t >> 5;          // 0..7
    const int bCol = (t & 31) * 4;    // 0..124

    float acc[8][8];
    #pragma unroll
    for (int i = 0; i < 8; i++)
        #pragma unroll
        for (int j = 0; j < 8; j++) acc[i][j] = 0.0f;

    for (int k0 = 0; k0 < K; k0 += 16) {
        #pragma unroll
        for (int p = 0; p < 2; p++) {
            int m = aRow + p * 64;
            float4 vA = *reinterpret_cast<const float4*>(
                &A[(size_t)(row0 + m) * K + k0 + aCol]);
            As[aCol + 0][m] = vA.x;
            As[aCol + 1][m] = vA.y;
            As[aCol + 2][m] = vA.z;
            As[aCol + 3][m] = vA.w;
        }
        #pragma unroll
        for (int p = 0; p < 2; p++) {
            int kk = bRow + p * 8;
            int c = col0 + bCol;
            float4 vB = make_float4(0.f, 0.f, 0.f, 0.f);
            if (c < N)
                vB = *reinterpret_cast<const float4*>(&B[(size_t)(k0 + kk) * N + c]);
            *reinterpret_cast<float4*>(&Bs[kk][bCol]) = vB;
        }
        __syncthreads();

        #pragma unroll
        for (int kk = 0; kk < 16; kk++) {
            float ra[8], rb[8];
            float4 a0 = *reinterpret_cast<const float4*>(&As[kk][ty * 8]);
            float4 a1 = *reinterpret_cast<const float4*>(&As[kk][ty * 8 + 4]);
            float4 b0 = *reinterpret_cast<const float4*>(&Bs[kk][tx * 8]);
            float4 b1 = *reinterpret_cast<const float4*>(&Bs[kk][tx * 8 + 4]);
            ra[0]=a0.x; ra[1]=a0.y; ra[2]=a0.z; ra[3]=a0.w;
            ra[4]=a1.x; ra[5]=a1.y; ra[6]=a1.z; ra[7]=a1.w;
            rb[0]=b0.x; rb[1]=b0.y; rb[2]=b0.z; rb[3]=b0.w;
            rb[4]=b1.x; rb[5]=b1.y; rb[6]=b1.z; rb[7]=b1.w;
            #pragma unroll
            for (int i = 0; i < 8; i++)
                #pragma unroll
                for (int j = 0; j < 8; j++)
                    acc[i][j] += ra[i] * rb[j];
        }
        __syncthreads();
    }

    #pragma unroll
    for (int i = 0; i < 8; i++) {
        int m = row0 + ty * 8 + i;
        #pragma unroll
        for (int j = 0; j < 8; j++) {
            int c = col0 + tx * 8 + j;
            if (c < N) {
                float val = acc[i][j];
                if (bias) val += bias[c];
                if (relu) val = fmaxf(val, 0.0f);
                C[(size_t)m * N + c] = val;
            }
        }
    }
}

// ---------------- QK^T with scale + causal mask -> logits[b,h,q,k] ----------------
__global__ __launch_bounds__(256) void qk_kernel(
    const float* __restrict__ Q, const float* __restrict__ Km,
    float* __restrict__ L, int causal)
{
    __shared__ float Qs[64][68];
    __shared__ float Ks[64][68];
    int bh = blockIdx.z, b = bh >> 3, h = bh & 7;
    int q0 = blockIdx.y * 64, k0 = blockIdx.x * 64;
    int t = threadIdx.x;

    #pragma unroll
    for (int p = 0; p < 4; p++) {
        int idx = t + p * 256;
        int r = idx >> 4, f4 = (idx & 15) * 4;
        *reinterpret_cast<float4*>(&Qs[r][f4]) =
            *reinterpret_cast<const float4*>(&Q[(size_t)(b * Ss + q0 + r) * Ee + h * HDm + f4]);
        *reinterpret_cast<float4*>(&Ks[r][f4]) =
            *reinterpret_cast<const float4*>(&Km[(size_t)(b * Ss + k0 + r) * Ee + h * HDm + f4]);
    }
    __syncthreads();

    int tx = t & 15, ty = t >> 4;
    float acc[4][4] = {};
    #pragma unroll 4
    for (int d = 0; d < 64; d++) {
        float ra[4], rb[4];
        #pragma unroll
        for (int i = 0; i < 4; i++) ra[i] = Qs[ty * 4 + i][d];
        #pragma unroll
        for (int j = 0; j < 4; j++) rb[j] = Ks[tx * 4 + j][d];
        #pragma unroll
        for (int i = 0; i < 4; i++)
            #pragma unroll
            for (int j = 0; j < 4; j++)
                acc[i][j] += ra[i] * rb[j];
    }

    #pragma unroll
    for (int i = 0; i < 4; i++) {
        int qi = q0 + ty * 4 + i;
        #pragma unroll
        for (int j = 0; j < 4; j++) {
            int ki = k0 + tx * 4 + j;
            float v = acc[i][j] * QK_SCALE;
            if (causal && ki > qi) v = -INFINITY;
            L[((size_t)bh * Ss + qi) * Ss + ki] = v;
        }
    }
}

// ---------------- row softmax over 512 cols ----------------
__global__ __launch_bounds__(256) void softmax_kernel(float* __restrict__ L)
{
    __shared__ float red[256];
    float* row = L + (size_t)blockIdx.x * Ss;
    int t = threadIdx.x;
    float a = row[t], b = row[t + 256];
    red[t] = fmaxf(a, b);
    __syncthreads();
    for (int s = 128; s > 0; s >>= 1) {
        if (t < s) red[t] = fmaxf(red[t], red[t + s]);
        __syncthreads();
    }
    float m = red[0];
    __syncthreads();
    float e0 = expf(a - m), e1 = expf(b - m);
    red[t] = e0 + e1;
    __syncthreads();
    for (int s = 128; s > 0; s >>= 1) {
        if (t < s) red[t] += red[t + s];
        __syncthreads();
    }
    float inv = 1.0f / red[0];
    row[t] = e0 * inv;
    row[t + 256] = e1 * inv;
}

// ---------------- P @ V -> att[b,q,h,d] ----------------
__global__ __launch_bounds__(256) void pv_kernel(
    const float* __restrict__ P, const float* __restrict__ V, float* __restrict__ O)
{
    __shared__ float Ps[64][68];
    __shared__ float Vs[64][68];
    int bh = blockIdx.y, b = bh >> 3, h = bh & 7;
    int q0 = blockIdx.x * 64;
    int t = threadIdx.x, tx = t & 15, ty = t >> 4;
    float acc[4][4] = {};

    for (int k0 = 0; k0 < Ss; k0 += 64) {
        #pragma unroll
        for (int p = 0; p < 4; p++) {
            int idx = t + p * 256;
            int r = idx >> 4, f4 = (idx & 15) * 4;
            *reinterpret_cast<float4*>(&Ps[r][f4]) =
                *reinterpret_cast<const float4*>(&P[((size_t)bh * Ss + q0 + r) * Ss + k0 + f4]);
            *reinterpret_cast<float4*>(&Vs[r][f4]) =
                *reinterpret_cast<const float4*>(&V[(size_t)(b * Ss + k0 + r) * Ee + h * HDm + f4]);
        }
        __syncthreads();
        #pragma unroll 4
        for (int kk = 0; kk < 64; kk++) {
            float ra[4], rb[4];
            #pragma unroll
            for (int i = 0; i < 4; i++) ra[i] = Ps[ty * 4 + i][kk];
            #pragma unroll
            for (int j = 0; j < 4; j++) rb[j] = Vs[kk][tx * 4 + j];
            #pragma unroll
            for (int i = 0; i < 4; i++)
                #pragma unroll
                for (int j = 0; j < 4; j++)
                    acc[i][j] += ra[i] * rb[j];
        }
        __syncthreads();
    }

    #pragma unroll
    for (int i = 0; i < 4; i++)
        #pragma unroll
        for (int j = 0; j < 4; j++)
            O[(size_t)(b * Ss + q0 + ty * 4 + i) * Ee + h * HDm + tx * 4 + j] = acc[i][j];
}

// ---------------- LayerNorm(out = LN(A + R) * g + b), optional relu ----------------
__global__ __launch_bounds__(256) void ln_kernel(
    const float* __restrict__ A, const float* __restrict__ R,
    const float* __restrict__ g, const float* __restrict__ be,
    float* __restrict__ out, int relu)
{
    __shared__ float red[256];
    size_t row = blockIdx.x;
    int t = threadIdx.x;
    float a0 = A[row * Ee + t] + R[row * Ee + t];
    float a1 = A[row * Ee + t + 256] + R[row * Ee + t + 256];

    red[t] = a0 + a1;
    __syncthreads();
    for (int s = 128; s > 0; s >>= 1) {
        if (t < s) red[t] += red[t + s];
        __syncthreads();
    }
    float mean = red[0] * (1.0f / Ee);
    __syncthreads();

    float d0 = a0 - mean, d1 = a1 - mean;
    red[t] = d0 * d0 + d1 * d1;
    __syncthreads();
    for (int s = 128; s > 0; s >>= 1) {
        if (t < s) red[t] += red[t + s];
        __syncthreads();
    }
    float var = red[0] * (1.0f / Ee);
    float inv = rsqrtf(var + LN_EPS);

    float v0 = d0 * inv * g[t] + be[t];
    float v1 = d1 * inv * g[t + 256] + be[t + 256];
    if (relu) { v0 = fmaxf(v0, 0.0f); v1 = fmaxf(v1, 0.0f); }
    out[row * Ee + t] = v0;
    out[row * Ee + t + 256] = v1;
}

// ---------------- host orchestration ----------------
static inline void launch_gemm(const float* A, const float* B, const float* bias,
                               float* C, int M, int N, int K, int relu)
{
    dim3 grid((N + 127) / 128, M / 128);
    sgemm_kernel<<<grid, 256>>>(A, B, bias, C, M, N, K, relu);
}

extern "C" void kernel_launch(void* const* d_in, const int* in_sizes, int n_in,
                              void* d_out, int out_size)
{
    const int*   src_ids  = (const int*)  d_in[0];
    const int*   tgt_ids  = (const int*)  d_in[1];
    const float* src_emb  = (const float*)d_in[2];
    const float* tgt_emb  = (const float*)d_in[3];
    const float* enc_wk   = (const float*)d_in[4];
    const float* enc_wv   = (const float*)d_in[5];
    const float* enc_wq   = (const float*)d_in[6];
    const float* enc_dw   = (const float*)d_in[7];
    const float* enc_db   = (const float*)d_in[8];
    const float* enc_ffw  = (const float*)d_in[9];
    const float* enc_ffb  = (const float*)d_in[10];
    const float* enc_ln_g = (const float*)d_in[11];
    const float* enc_ln_b = (const float*)d_in[12];
    const float* dec_swk  = (const float*)d_in[13];
    const float* dec_swv  = (const float*)d_in[14];
    const float* dec_swq  = (const float*)d_in[15];
    const float* dec_sdw  = (const float*)d_in[16];
    const float* dec_sdb  = (const float*)d_in[17];
    const float* dec_cwk  = (const float*)d_in[18];
    const float* dec_cwv  = (const float*)d_in[19];
    const float* dec_cwq  = (const float*)d_in[20];
    const float* dec_cdw  = (const float*)d_in[21];
    const float* dec_cdb  = (const float*)d_in[22];
    const float* dec_ffw  = (const float*)d_in[23];
    const float* dec_ffb  = (const float*)d_in[24];
    const float* dec_ln_g = (const float*)d_in[25];
    const float* dec_ln_b = (const float*)d_in[26];
    const float* cls_w1   = (const float*)d_in[27];
    const float* cls_b1   = (const float*)d_in[28];
    const float* cls_w2   = (const float*)d_in[29];
    const float* cls_b2   = (const float*)d_in[30];

    float *x, *y, *q, *k, *v, *att, *t0, *t1, *t2, *w, *logits, *hid;
    cudaGetSymbolAddress((void**)&x,      g_x);
    cudaGetSymbolAddress((void**)&y,      g_y);
    cudaGetSymbolAddress((void**)&q,      g_q);
    cudaGetSymbolAddress((void**)&k,      g_k);
    cudaGetSymbolAddress((void**)&v,      g_v);
    cudaGetSymbolAddress((void**)&att,    g_att);
    cudaGetSymbolAddress((void**)&t0,     g_t0);
    cudaGetSymbolAddress((void**)&t1,     g_t1);
    cudaGetSymbolAddress((void**)&t2,     g_t2);
    cudaGetSymbolAddress((void**)&w,      g_w);
    cudaGetSymbolAddress((void**)&logits, g_logits);
    cudaGetSymbolAddress((void**)&hid,    g_hid);

    // embeddings + positional encoding
    embed_kernel<<<ROWS, 256>>>(src_ids, src_emb, x);
    embed_kernel<<<ROWS, 256>>>(tgt_ids, tgt_emb, y);

    // multi-head attention macro: out = concat_heads(softmax(QK^T/sqrt(512) [+mask]) V) @ dw + db
    #define RUN_MHA(Xk, Xv, Xq, wk_, wv_, wq_, dw_, db_, OUT, CAUSAL)              \
        do {                                                                       \
            repack_kernel<<<Ee, 256>>>((wq_), w);                                  \
            launch_gemm((Xq), w, nullptr, q, ROWS, Ee, Ee, 0);                     \
            repack_kernel<<<Ee, 256>>>((wk_), w);                                  \
            launch_gemm((Xk), w, nullptr, k, ROWS, Ee, Ee, 0);                     \
            repack_kernel<<<Ee, 256>>>((wv_), w);                                  \
            launch_gemm((Xv), w, nullptr, v, ROWS, Ee, Ee, 0);                     \
            qk_kernel<<<dim3(8, 8, Bb * NH), 256>>>(q, k, logits, (CAUSAL));       \
            softmax_kernel<<<Bb * NH * Ss, 256>>>(logits);                         \
            pv_kernel<<<dim3(8, Bb * NH), 256>>>(logits, v, att);                  \
            launch_gemm(att, (dw_), (db_), (OUT), ROWS, Ee, Ee, 0);                \
        } while (0)

    // ---- encoder block (self-attn is causal in the original) ----
    RUN_MHA(x, x, x, enc_wk, enc_wv, enc_wq, enc_dw, enc_db, t0, 1);   // a
    ln_kernel<<<ROWS, 256>>>(x, t0, enc_ln_g, enc_ln_b, t1, 0);        // h = LN(x+a)
    launch_gemm(t1, enc_ffw, enc_ffb, t2, ROWS, Ee, Ee, 0);            // f
    ln_kernel<<<ROWS, 256>>>(t1, t2, enc_ln_g, enc_ln_b, x, 0);        // enc_out -> x

    // ---- decoder block ----
    RUN_MHA(y, y, y, dec_swk, dec_swv, dec_swq, dec_sdw, dec_sdb, t0, 1);  // sa
    ln_kernel<<<ROWS, 256>>>(t0, y, dec_ln_g, dec_ln_b, t1, 0);            // h1
    // cross-attn: K,V from enc_out (x), Q from h1 (t1)
    RUN_MHA(x, x, t1, dec_cwk, dec_cwv, dec_cwq, dec_cdw, dec_cdb, t0, 0); // ca
    ln_kernel<<<ROWS, 256>>>(t0, t1, dec_ln_g, dec_ln_b, t2, 0);           // h2
    launch_gemm(t2, dec_ffw, dec_ffb, t0, ROWS, Ee, Ee, 0);                // f2
    ln_kernel<<<ROWS, 256>>>(t0, t2, dec_ln_g, dec_ln_b, t1, 1);           // dec_out = relu(LN(f2+h2))

    // ---- classifier ----
    launch_gemm(t1, cls_w1, cls_b1, hid, ROWS, CLS_H, Ee, 1);              // hid = relu(. @ w1 + b1)
    launch_gemm(hid, cls_w2, cls_b2, (float*)d_out, ROWS, VOC, CLS_H, 0);  // out

    #undef RUN_MHA
}

// round 5
// speedup vs baseline: 1.8475x; 1.8475x over previous
#include <cuda_runtime.h>
#include <cuda_bf16.h>
#include <math.h>
#include <stdint.h>

// Problem dims
#define Bb 8
#define Ss 512
#define Ee 512
#define NH 8
#define HDm 64
#define ROWS (Bb*Ss)        // 4096 token rows
#define CLS_H 16000
#define VOC 8000
#define VOC_PAD 8064
#define SQRT_E 22.627416997969522f
#define QK_SCALE 0.04419417382415922f   // 1/sqrt(512)
#define LN_EPS 1e-3f

// ---------------- scratch (device globals; no allocations allowed) -------------
__device__ float g_x[ROWS*Ee];
__device__ float g_y[ROWS*Ee];
__device__ float g_q[ROWS*Ee];
__device__ float g_k[ROWS*Ee];
__device__ float g_v[ROWS*Ee];
__device__ float g_att[ROWS*Ee];
__device__ float g_t0[ROWS*Ee];
__device__ float g_t1[ROWS*Ee];
__device__ float g_t2[ROWS*Ee];
__device__ float g_w[Ee*Ee];
__device__ float g_logits[Bb*NH*Ss*Ss];

// bf16 split buffers for the tensor-core classifier path
__device__ __nv_bfloat16 g_A1h[ROWS*Ee];
__device__ __nv_bfloat16 g_A1l[ROWS*Ee];
__device__ __nv_bfloat16 g_B1h[(size_t)CLS_H*Ee];      // w1^T [16000,512]
__device__ __nv_bfloat16 g_B1l[(size_t)CLS_H*Ee];
__device__ __nv_bfloat16 g_A2h[(size_t)ROWS*CLS_H];    // hidden [4096,16000]
__device__ __nv_bfloat16 g_A2l[(size_t)ROWS*CLS_H];
__device__ __nv_bfloat16 g_B2h[(size_t)VOC_PAD*CLS_H]; // w2^T padded [8064,16000]
__device__ __nv_bfloat16 g_B2l[(size_t)VOC_PAD*CLS_H];

// ================= helpers =================
__device__ __forceinline__ uint32_t smem_u32(const void* p) {
    uint32_t a;
    asm("{ .reg .u64 t; cvta.to.shared.u64 t, %1; cvt.u32.u64 %0, t; }" : "=r"(a) : "l"(p));
    return a;
}
__device__ __forceinline__ void cp16(uint32_t dst, const void* src) {
    asm volatile("cp.async.cg.shared.global [%0], [%1], 16;" :: "r"(dst), "l"(src));
}
__device__ __forceinline__ void cp_commit() { asm volatile("cp.async.commit_group;"); }
__device__ __forceinline__ void cp_wait1()  { asm volatile("cp.async.wait_group 1;"); }

__device__ __forceinline__ void ldsm4(uint32_t* r, uint32_t addr) {
    asm volatile("ldmatrix.sync.aligned.m8n8.x4.shared.b16 {%0,%1,%2,%3}, [%4];"
        : "=r"(r[0]), "=r"(r[1]), "=r"(r[2]), "=r"(r[3]) : "r"(addr));
}
__device__ __forceinline__ void mma_bf16(float* c, const uint32_t* a, const uint32_t* b) {
    asm volatile("mma.sync.aligned.m16n8k16.row.col.f32.bf16.bf16.f32 "
        "{%0,%1,%2,%3}, {%4,%5,%6,%7}, {%8,%9}, {%0,%1,%2,%3};"
        : "+f"(c[0]), "+f"(c[1]), "+f"(c[2]), "+f"(c[3])
        : "r"(a[0]), "r"(a[1]), "r"(a[2]), "r"(a[3]), "r"(b[0]), "r"(b[1]));
}

// ================= split-bf16 HMMA GEMM =================
// C[M,N] = (Ah+Al)[M,K] @ (Bh+Bl)[N,K]^T ; 128x128 CTA tile, K chunks of 32.
// mode 0: out = relu(acc+bias) -> split bf16 (oh, ol)   (classifier GEMM1)
// mode 1: outf = acc + bias, guarded to col < Nreal     (classifier GEMM2)
// SMEM stage: Ah,Al,Bh,Bl each [128][32] bf16 padded to row stride 40 elem (80B)
#define MAT_BYTES 10240            // 128*40*2
#define STAGE_BYTES (4*MAT_BYTES)  // 40960
#define NSTAGE 3

__device__ __forceinline__ void load_stage(
    uint32_t sb, const __nv_bfloat16* Ah, const __nv_bfloat16* Al,
    const __nv_bfloat16* Bh, const __nv_bfloat16* Bl,
    size_t m0, size_t n0, int k0, int lda, int ldb, int t)
{
    const __nv_bfloat16* srcs[4] = { Ah, Al, Bh, Bl };
    #pragma unroll
    for (int p = 0; p < 8; p++) {
        int idx = t + p * 256;           // 0..2047
        int mat = idx >> 9;              // 0..3
        int r   = (idx & 511) >> 2;      // 0..127
        int ch  = idx & 3;               // 16B chunk in row
        size_t grow = (mat < 2 ? m0 : n0) + r;
        int ld = (mat < 2 ? lda : ldb);
        const __nv_bfloat16* src = srcs[mat] + grow * (size_t)ld + k0 + ch * 8;
        cp16(sb + mat * MAT_BYTES + r * 80 + ch * 16, src);
    }
}

__global__ void __launch_bounds__(256) gemm_mma_kernel(
    const __nv_bfloat16* __restrict__ Ah, const __nv_bfloat16* __restrict__ Al,
    const __nv_bfloat16* __restrict__ Bh, const __nv_bfloat16* __restrict__ Bl,
    const float* __restrict__ bias, float* __restrict__ outf,
    __nv_bfloat16* __restrict__ oh, __nv_bfloat16* __restrict__ ol,
    int K, int lda, int ldb, int tiles_n, int Nreal, int ldo, int mode)
{
    extern __shared__ char smem[];
    uint32_t sbase = smem_u32(smem);
    const int t = threadIdx.x;
    const int wid = t >> 5, lane = t & 31;
    const int warp_m = wid & 1, warp_n = wid >> 1;   // 2x4 warps, warp tile 64x32

    // tile mapping with M-band grouping of 8 for L2 reuse
    const int G = 8;
    int idx = blockIdx.x;
    int band = idx / (G * tiles_n);
    int r = idx % (G * tiles_n);
    size_t m0 = (size_t)(band * G + (r % G)) * 128;
    size_t n0 = (size_t)(r / G) * 128;

    float acc[4][4][4];
    #pragma unroll
    for (int i = 0; i < 4; i++)
        #pragma unroll
        for (int j = 0; j < 4; j++)
            #pragma unroll
            for (int e = 0; e < 4; e++) acc[i][j][e] = 0.0f;

    const int C = K >> 5;   // K chunks of 32
    load_stage(sbase + 0 * STAGE_BYTES, Ah, Al, Bh, Bl, m0, n0, 0,  lda, ldb, t); cp_commit();
    load_stage(sbase + 1 * STAGE_BYTES, Ah, Al, Bh, Bl, m0, n0, 32, lda, ldb, t); cp_commit();

    const int lrow = lane & 15;
    const int lcolb = (lane >> 4) * 16;   // byte offset of 8-elem half

    for (int c = 0; c < C; c++) {
        cp_wait1();
        __syncthreads();
        if (c + 2 < C)
            load_stage(sbase + ((c + 2) % NSTAGE) * STAGE_BYTES,
                       Ah, Al, Bh, Bl, m0, n0, (c + 2) * 32, lda, ldb, t);
        cp_commit();

        uint32_t sb = sbase + (c % NSTAGE) * STAGE_BYTES;
        uint32_t aBaseH = sb +                (warp_m * 64 + lrow) * 80;
        uint32_t aBaseL = sb + MAT_BYTES    + (warp_m * 64 + lrow) * 80;
        uint32_t bBaseH = sb + 2*MAT_BYTES  + (warp_n * 32 + lrow) * 80;
        uint32_t bBaseL = sb + 3*MAT_BYTES  + (warp_n * 32 + lrow) * 80;

        #pragma unroll
        for (int ks = 0; ks < 2; ks++) {
            int kb = ks * 32 + lcolb;    // byte offset within row
            uint32_t ah[4][4], al[4][4], bh[4][2], bl[4][2];
            #pragma unroll
            for (int fm = 0; fm < 4; fm++) {
                ldsm4(ah[fm], aBaseH + fm * 16 * 80 + kb);
                ldsm4(al[fm], aBaseL + fm * 16 * 80 + kb);
            }
            #pragma unroll
            for (int fp = 0; fp < 2; fp++) {
                uint32_t rr[4];
                ldsm4(rr, bBaseH + fp * 16 * 80 + kb);
                bh[fp*2][0] = rr[0]; bh[fp*2][1] = rr[2];
                bh[fp*2+1][0] = rr[1]; bh[fp*2+1][1] = rr[3];
                ldsm4(rr, bBaseL + fp * 16 * 80 + kb);
                bl[fp*2][0] = rr[0]; bl[fp*2][1] = rr[2];
                bl[fp*2+1][0] = rr[1]; bl[fp*2+1][1] = rr[3];
            }
            #pragma unroll
            for (int fm = 0; fm < 4; fm++)
                #pragma unroll
                for (int fn = 0; fn < 4; fn++) {
                    mma_bf16(acc[fm][fn], ah[fm], bh[fn]);
                    mma_bf16(acc[fm][fn], al[fm], bh[fn]);
                    mma_bf16(acc[fm][fn], ah[fm], bl[fn]);
                }
        }
        __syncthreads();
    }

    // epilogue: frag (fm,fn): rows m0+warp_m*64+fm*16+{g,g+8}, cols n0+warp_n*32+fn*8+(lane%4)*2
    const int g = lane >> 2;
    const int cq = (lane & 3) * 2;
    #pragma unroll
    for (int fm = 0; fm < 4; fm++) {
        #pragma unroll
        for (int fn = 0; fn < 4; fn++) {
            int colbase = (int)n0 + warp_n * 32 + fn * 8 + cq;
            float b0 = bias[colbase], b1 = bias[colbase + 1];
            #pragma unroll
            for (int hrow = 0; hrow < 2; hrow++) {
                size_t row = m0 + warp_m * 64 + fm * 16 + g + hrow * 8;
                float v0 = acc[fm][fn][hrow * 2 + 0] + b0;
                float v1 = acc[fm][fn][hrow * 2 + 1] + b1;
                if (mode == 0) {
                    v0 = fmaxf(v0, 0.0f); v1 = fmaxf(v1, 0.0f);
                    __nv_bfloat16 h0 = __float2bfloat16(v0);
                    __nv_bfloat16 h1 = __float2bfloat16(v1);
                    __nv_bfloat162 hv, lv;
                    hv.x = h0; hv.y = h1;
                    lv.x = __float2bfloat16(v0 - __bfloat162float(h0));
                    lv.y = __float2bfloat16(v1 - __bfloat162float(h1));
                    *reinterpret_cast<__nv_bfloat162*>(&oh[row * (size_t)ldo + colbase]) = hv;
                    *reinterpret_cast<__nv_bfloat162*>(&ol[row * (size_t)ldo + colbase]) = lv;
                } else {
                    if (colbase < Nreal) {
                        float2 fv; fv.x = v0; fv.y = v1;
                        *reinterpret_cast<float2*>(&outf[row * (size_t)ldo + colbase]) = fv;
                    }
                }
            }
        }
    }
}

// ---------------- fp32 -> bf16 hi/lo split (elementwise) ----------------
__global__ __launch_bounds__(256) void split_kernel(
    const float* __restrict__ in, __nv_bfloat16* __restrict__ oh,
    __nv_bfloat16* __restrict__ ol, int count)
{
    int i = blockIdx.x * 256 + threadIdx.x;
    if (i < count) {
        float v = in[i];
        __nv_bfloat16 h = __float2bfloat16(v);
        oh[i] = h;
        ol[i] = __float2bfloat16(v - __bfloat162float(h));
    }
}

// ---------------- transpose + split: fp32 [K,N] -> bf16 [Npad,K] hi/lo ----------------
__global__ __launch_bounds__(256) void transpose_split_kernel(
    const float* __restrict__ in, __nv_bfloat16* __restrict__ oh,
    __nv_bfloat16* __restrict__ ol, int K, int N)
{
    __shared__ float tile[32][33];
    int n0 = blockIdx.x * 32, k0 = blockIdx.y * 32;
    int tx = threadIdx.x & 31, ty = threadIdx.x >> 5;  // block 256 = 32x8
    #pragma unroll
    for (int j = 0; j < 4; j++) {
        int kk = k0 + ty + j * 8;
        int nn = n0 + tx;
        tile[ty + j * 8][tx] = (nn < N) ? in[(size_t)kk * N + nn] : 0.0f;
    }
    __syncthreads();
    #pragma unroll
    for (int j = 0; j < 4; j++) {
        int nn = n0 + ty + j * 8;
        int kk = k0 + tx;
        float v = tile[tx][ty + j * 8];
        __nv_bfloat16 h = __float2bfloat16(v);
        oh[(size_t)nn * K + kk] = h;
        ol[(size_t)nn * K + kk] = __float2bfloat16(v - __bfloat162float(h));
    }
}

// ---------------- embedding + positional encoding ----------------
__global__ __launch_bounds__(256) void embed_kernel(
    const int* __restrict__ ids, const float* __restrict__ emb, float* __restrict__ out)
{
    int bs = blockIdx.x;
    int s  = bs & (Ss - 1);
    int id = ids[bs];
    const float* erow = emb + (size_t)id * Ee;
    float* orow = out + (size_t)bs * Ee;
    for (int e = threadIdx.x; e < Ee; e += blockDim.x) {
        int i = e & 255;
        float rate = expf(-(float)i * (9.210340371976184f / 256.0f));
        float ang = (float)s * rate;
        float p = (e < 256) ? sinf(ang) : cosf(ang);
        orow[e] = erow[e] * SQRT_E + p;
    }
}

// ---------------- repack [H,E,HD] -> [E, H*HD] ----------------
__global__ __launch_bounds__(256) void repack_kernel(
    const float* __restrict__ w, float* __restrict__ out)
{
    int e = blockIdx.x;
    for (int j = threadIdx.x; j < Ee; j += blockDim.x)
        out[e * Ee + j] = w[(j >> 6) * (Ee * HDm) + e * HDm + (j & 63)];
}

// ---------------- fp32 tiled SGEMM (E-size ops) ----------------
__global__ __launch_bounds__(256) void sgemm_kernel(
    const float* __restrict__ A, const float* __restrict__ B,
    const float* __restrict__ bias, float* __restrict__ C,
    int M, int N, int K, int relu)
{
    __shared__ float As[16][128];
    __shared__ float Bs[16][128];
    const int t  = threadIdx.x;
    const int tx = t & 15, ty = t >> 4;
    const int row0 = blockIdx.y * 128, col0 = blockIdx.x * 128;
    const int aRow = t >> 2, aCol = (t & 3) * 4;
    const int bRow = t >> 5, bCol = (t & 31) * 4;

    float acc[8][8];
    #pragma unroll
    for (int i = 0; i < 8; i++)
        #pragma unroll
        for (int j = 0; j < 8; j++) acc[i][j] = 0.0f;

    for (int k0 = 0; k0 < K; k0 += 16) {
        #pragma unroll
        for (int p = 0; p < 2; p++) {
            int m = aRow + p * 64;
            float4 vA = *reinterpret_cast<const float4*>(&A[(size_t)(row0 + m) * K + k0 + aCol]);
            As[aCol + 0][m] = vA.x; As[aCol + 1][m] = vA.y;
            As[aCol + 2][m] = vA.z; As[aCol + 3][m] = vA.w;
        }
        #pragma unroll
        for (int p = 0; p < 2; p++) {
            int kk = bRow + p * 8;
            int c = col0 + bCol;
            float4 vB = make_float4(0.f, 0.f, 0.f, 0.f);
            if (c < N) vB = *reinterpret_cast<const float4*>(&B[(size_t)(k0 + kk) * N + c]);
            *reinterpret_cast<float4*>(&Bs[kk][bCol]) = vB;
        }
        __syncthreads();
        #pragma unroll
        for (int kk = 0; kk < 16; kk++) {
            float ra[8], rb[8];
            float4 a0 = *reinterpret_cast<const float4*>(&As[kk][ty * 8]);
            float4 a1 = *reinterpret_cast<const float4*>(&As[kk][ty * 8 + 4]);
            float4 b0 = *reinterpret_cast<const float4*>(&Bs[kk][tx * 8]);
            float4 b1 = *reinterpret_cast<const float4*>(&Bs[kk][tx * 8 + 4]);
            ra[0]=a0.x; ra[1]=a0.y; ra[2]=a0.z; ra[3]=a0.w;
            ra[4]=a1.x; ra[5]=a1.y; ra[6]=a1.z; ra[7]=a1.w;
            rb[0]=b0.x; rb[1]=b0.y; rb[2]=b0.z; rb[3]=b0.w;
            rb[4]=b1.x; rb[5]=b1.y; rb[6]=b1.z; rb[7]=b1.w;
            #pragma unroll
            for (int i = 0; i < 8; i++)
                #pragma unroll
                for (int j = 0; j < 8; j++)
                    acc[i][j] += ra[i] * rb[j];
        }
        __syncthreads();
    }
    #pragma unroll
    for (int i = 0; i < 8; i++) {
        int m = row0 + ty * 8 + i;
        #pragma unroll
        for (int j = 0; j < 8; j++) {
            int c = col0 + tx * 8 + j;
            if (c < N) {
                float val = acc[i][j];
                if (bias) val += bias[c];
                if (relu) val = fmaxf(val, 0.0f);
                C[(size_t)m * N + c] = val;
            }
        }
    }
}

// ---------------- QK^T + scale + causal ----------------
__global__ __launch_bounds__(256) void qk_kernel(
    const float* __restrict__ Q, const float* __restrict__ Km,
    float* __restrict__ L, int causal)
{
    __shared__ float Qs[64][68];
    __shared__ float Ks[64][68];
    int bh = blockIdx.z, b = bh >> 3, h = bh & 7;
    int q0 = blockIdx.y * 64, k0 = blockIdx.x * 64;
    int t = threadIdx.x;
    #pragma unroll
    for (int p = 0; p < 4; p++) {
        int idx = t + p * 256;
        int r = idx >> 4, f4 = (idx & 15) * 4;
        *reinterpret_cast<float4*>(&Qs[r][f4]) =
            *reinterpret_cast<const float4*>(&Q[(size_t)(b * Ss + q0 + r) * Ee + h * HDm + f4]);
        *reinterpret_cast<float4*>(&Ks[r][f4]) =
            *reinterpret_cast<const float4*>(&Km[(size_t)(b * Ss + k0 + r) * Ee + h * HDm + f4]);
    }
    __syncthreads();
    int tx = t & 15, ty = t >> 4;
    float acc[4][4] = {};
    #pragma unroll 4
    for (int d = 0; d < 64; d++) {
        float ra[4], rb[4];
        #pragma unroll
        for (int i = 0; i < 4; i++) ra[i] = Qs[ty * 4 + i][d];
        #pragma unroll
        for (int j = 0; j < 4; j++) rb[j] = Ks[tx * 4 + j][d];
        #pragma unroll
        for (int i = 0; i < 4; i++)
            #pragma unroll
            for (int j = 0; j < 4; j++)
                acc[i][j] += ra[i] * rb[j];
    }
    #pragma unroll
    for (int i = 0; i < 4; i++) {
        int qi = q0 + ty * 4 + i;
        #pragma unroll
        for (int j = 0; j < 4; j++) {
            int ki = k0 + tx * 4 + j;
            float v = acc[i][j] * QK_SCALE;
            if (causal && ki > qi) v = -INFINITY;
            L[((size_t)bh * Ss + qi) * Ss + ki] = v;
        }
    }
}

// ---------------- row softmax ----------------
__global__ __launch_bounds__(256) void softmax_kernel(float* __restrict__ L)
{
    __shared__ float red[256];
    float* row = L + (size_t)blockIdx.x * Ss;
    int t = threadIdx.x;
    float a = row[t], b = row[t + 256];
    red[t] = fmaxf(a, b);
    __syncthreads();
    for (int s = 128; s > 0; s >>= 1) { if (t < s) red[t] = fmaxf(red[t], red[t + s]); __syncthreads(); }
    float m = red[0];
    __syncthreads();
    float e0 = expf(a - m), e1 = expf(b - m);
    red[t] = e0 + e1;
    __syncthreads();
    for (int s = 128; s > 0; s >>= 1) { if (t < s) red[t] += red[t + s]; __syncthreads(); }
    float inv = 1.0f / red[0];
    row[t] = e0 * inv;
    row[t + 256] = e1 * inv;
}

// ---------------- P @ V ----------------
__global__ __launch_bounds__(256) void pv_kernel(
    const float* __restrict__ P, const float* __restrict__ V, float* __restrict__ O)
{
    __shared__ float Ps[64][68];
    __shared__ float Vs[64][68];
    int bh = blockIdx.y, b = bh >> 3, h = bh & 7;
    int q0 = blockIdx.x * 64;
    int t = threadIdx.x, tx = t & 15, ty = t >> 4;
    float acc[4][4] = {};
    for (int k0 = 0; k0 < Ss; k0 += 64) {
        #pragma unroll
        for (int p = 0; p < 4; p++) {
            int idx = t + p * 256;
            int r = idx >> 4, f4 = (idx & 15) * 4;
            *reinterpret_cast<float4*>(&Ps[r][f4]) =
                *reinterpret_cast<const float4*>(&P[((size_t)bh * Ss + q0 + r) * Ss + k0 + f4]);
            *reinterpret_cast<float4*>(&Vs[r][f4]) =
                *reinterpret_cast<const float4*>(&V[(size_t)(b * Ss + k0 + r) * Ee + h * HDm + f4]);
        }
        __syncthreads();
        #pragma unroll 4
        for (int kk = 0; kk < 64; kk++) {
            float ra[4], rb[4];
            #pragma unroll
            for (int i = 0; i < 4; i++) ra[i] = Ps[ty * 4 + i][kk];
            #pragma unroll
            for (int j = 0; j < 4; j++) rb[j] = Vs[kk][tx * 4 + j];
            #pragma unroll
            for (int i = 0; i < 4; i++)
                #pragma unroll
                for (int j = 0; j < 4; j++)
                    acc[i][j] += ra[i] * rb[j];
        }
        __syncthreads();
    }
    #pragma unroll
    for (int i = 0; i < 4; i++)
        #pragma unroll
        for (int j = 0; j < 4; j++)
            O[(size_t)(b * Ss + q0 + ty * 4 + i) * Ee + h * HDm + tx * 4 + j] = acc[i][j];
}

// ---------------- LN(A + R)*g + b (opt relu) ----------------
__global__ __launch_bounds__(256) void ln_kernel(
    const float* __restrict__ A, const float* __restrict__ R,
    const float* __restrict__ g, const float* __restrict__ be,
    float* __restrict__ out, int relu)
{
    __shared__ float red[256];
    size_t row = blockIdx.x;
    int t = threadIdx.x;
    float a0 = A[row * Ee + t] + R[row * Ee + t];
    float a1 = A[row * Ee + t + 256] + R[row * Ee + t + 256];
    red[t] = a0 + a1;
    __syncthreads();
    for (int s = 128; s > 0; s >>= 1) { if (t < s) red[t] += red[t + s]; __syncthreads(); }
    float mean = red[0] * (1.0f / Ee);
    __syncthreads();
    float d0 = a0 - mean, d1 = a1 - mean;
    red[t] = d0 * d0 + d1 * d1;
    __syncthreads();
    for (int s = 128; s > 0; s >>= 1) { if (t < s) red[t] += red[t + s]; __syncthreads(); }
    float var = red[0] * (1.0f / Ee);
    float inv = rsqrtf(var + LN_EPS);
    float v0 = d0 * inv * g[t] + be[t];
    float v1 = d1 * inv * g[t + 256] + be[t + 256];
    if (relu) { v0 = fmaxf(v0, 0.0f); v1 = fmaxf(v1, 0.0f); }
    out[row * Ee + t] = v0;
    out[row * Ee + t + 256] = v1;
}

// ---------------- host orchestration ----------------
static inline void launch_gemm(const float* A, const float* B, const float* bias,
                               float* C, int M, int N, int K, int relu)
{
    dim3 grid((N + 127) / 128, M / 128);
    sgemm_kernel<<<grid, 256>>>(A, B, bias, C, M, N, K, relu);
}

extern "C" void kernel_launch(void* const* d_in, const int* in_sizes, int n_in,
                              void* d_out, int out_size)
{
    const int*   src_ids  = (const int*)  d_in[0];
    const int*   tgt_ids  = (const int*)  d_in[1];
    const float* src_emb  = (const float*)d_in[2];
    const float* tgt_emb  = (const float*)d_in[3];
    const float* enc_wk   = (const float*)d_in[4];
    const float* enc_wv   = (const float*)d_in[5];
    const float* enc_wq   = (const float*)d_in[6];
    const float* enc_dw   = (const float*)d_in[7];
    const float* enc_db   = (const float*)d_in[8];
    const float* enc_ffw  = (const float*)d_in[9];
    const float* enc_ffb  = (const float*)d_in[10];
    const float* enc_ln_g = (const float*)d_in[11];
    const float* enc_ln_b = (const float*)d_in[12];
    const float* dec_swk  = (const float*)d_in[13];
    const float* dec_swv  = (const float*)d_in[14];
    const float* dec_swq  = (const float*)d_in[15];
    const float* dec_sdw  = (const float*)d_in[16];
    const float* dec_sdb  = (const float*)d_in[17];
    const float* dec_cwk  = (const float*)d_in[18];
    const float* dec_cwv  = (const float*)d_in[19];
    const float* dec_cwq  = (const float*)d_in[20];
    const float* dec_cdw  = (const float*)d_in[21];
    const float* dec_cdb  = (const float*)d_in[22];
    const float* dec_ffw  = (const float*)d_in[23];
    const float* dec_ffb  = (const float*)d_in[24];
    const float* dec_ln_g = (const float*)d_in[25];
    const float* dec_ln_b = (const float*)d_in[26];
    const float* cls_w1   = (const float*)d_in[27];
    const float* cls_b1   = (const float*)d_in[28];
    const float* cls_w2   = (const float*)d_in[29];
    const float* cls_b2   = (const float*)d_in[30];

    float *x, *y, *q, *k, *v, *att, *t0, *t1, *t2, *w, *logits;
    __nv_bfloat16 *A1h, *A1l, *B1h, *B1l, *A2h, *A2l, *B2h, *B2l;
    cudaGetSymbolAddress((void**)&x,      g_x);
    cudaGetSymbolAddress((void**)&y,      g_y);
    cudaGetSymbolAddress((void**)&q,      g_q);
    cudaGetSymbolAddress((void**)&k,      g_k);
    cudaGetSymbolAddress((void**)&v,      g_v);
    cudaGetSymbolAddress((void**)&att,    g_att);
    cudaGetSymbolAddress((void**)&t0,     g_t0);
    cudaGetSymbolAddress((void**)&t1,     g_t1);
    cudaGetSymbolAddress((void**)&t2,     g_t2);
    cudaGetSymbolAddress((void**)&w,      g_w);
    cudaGetSymbolAddress((void**)&logits, g_logits);
    cudaGetSymbolAddress((void**)&A1h, g_A1h);
    cudaGetSymbolAddress((void**)&A1l, g_A1l);
    cudaGetSymbolAddress((void**)&B1h, g_B1h);
    cudaGetSymbolAddress((void**)&B1l, g_B1l);
    cudaGetSymbolAddress((void**)&A2h, g_A2h);
    cudaGetSymbolAddress((void**)&A2l, g_A2l);
    cudaGetSymbolAddress((void**)&B2h, g_B2h);
    cudaGetSymbolAddress((void**)&B2l, g_B2l);

    static bool attr_set = false;
    if (!attr_set) {
        cudaFuncSetAttribute(gemm_mma_kernel, cudaFuncAttributeMaxDynamicSharedMemorySize,
                             NSTAGE * STAGE_BYTES);
        attr_set = true;
    }
    const int TC_SMEM = NSTAGE * STAGE_BYTES;

    // weight prep for tensor-core classifier (independent of activations)
    transpose_split_kernel<<<dim3(CLS_H / 32, Ee / 32), 256>>>(cls_w1, B1h, B1l, Ee, CLS_H);
    transpose_split_kernel<<<dim3(VOC_PAD / 32, CLS_H / 32), 256>>>(cls_w2, B2h, B2l, CLS_H, VOC);

    // embeddings + positional encoding
    embed_kernel<<<ROWS, 256>>>(src_ids, src_emb, x);
    embed_kernel<<<ROWS, 256>>>(tgt_ids, tgt_emb, y);

    #define RUN_MHA(Xk, Xv, Xq, wk_, wv_, wq_, dw_, db_, OUT, CAUSAL)              \
        do {                                                                       \
            repack_kernel<<<Ee, 256>>>((wq_), w);                                  \
            launch_gemm((Xq), w, nullptr, q, ROWS, Ee, Ee, 0);                     \
            repack_kernel<<<Ee, 256>>>((wk_), w);                                  \
            launch_gemm((Xk), w, nullptr, k, ROWS, Ee, Ee, 0);                     \
            repack_kernel<<<Ee, 256>>>((wv_), w);                                  \
            launch_gemm((Xv), w, nullptr, v, ROWS, Ee, Ee, 0);                     \
            qk_kernel<<<dim3(8, 8, Bb * NH), 256>>>(q, k, logits, (CAUSAL));       \
            softmax_kernel<<<Bb * NH * Ss, 256>>>(logits);                         \
            pv_kernel<<<dim3(8, Bb * NH), 256>>>(logits, v, att);                  \
            launch_gemm(att, (dw_), (db_), (OUT), ROWS, Ee, Ee, 0);                \
        } while (0)

    // ---- encoder ----
    RUN_MHA(x, x, x, enc_wk, enc_wv, enc_wq, enc_dw, enc_db, t0, 1);
    ln_kernel<<<ROWS, 256>>>(x, t0, enc_ln_g, enc_ln_b, t1, 0);
    launch_gemm(t1, enc_ffw, enc_ffb, t2, ROWS, Ee, Ee, 0);
    ln_kernel<<<ROWS, 256>>>(t1, t2, enc_ln_g, enc_ln_b, x, 0);

    // ---- decoder ----
    RUN_MHA(y, y, y, dec_swk, dec_swv, dec_swq, dec_sdw, dec_sdb, t0, 1);
    ln_kernel<<<ROWS, 256>>>(t0, y, dec_ln_g, dec_ln_b, t1, 0);
    RUN_MHA(x, x, t1, dec_cwk, dec_cwv, dec_cwq, dec_cdw, dec_cdb, t0, 0);
    ln_kernel<<<ROWS, 256>>>(t0, t1, dec_ln_g, dec_ln_b, t2, 0);
    launch_gemm(t2, dec_ffw, dec_ffb, t0, ROWS, Ee, Ee, 0);
    ln_kernel<<<ROWS, 256>>>(t0, t2, dec_ln_g, dec_ln_b, t1, 1);  // dec_out

    // ---- classifier on HMMA (split-bf16) ----
    split_kernel<<<(ROWS * Ee + 255) / 256, 256>>>(t1, A1h, A1l, ROWS * Ee);
    // GEMM1: [4096,512] @ [512,16000] -> relu -> split bf16 hidden
    gemm_mma_kernel<<<(ROWS / 128) * (CLS_H / 128), 256, TC_SMEM>>>(
        A1h, A1l, B1h, B1l, cls_b1, nullptr, A2h, A2l,
        Ee, Ee, Ee, CLS_H / 128, CLS_H, CLS_H, 0);
    // GEMM2: [4096,16000] @ [16000,8000] -> fp32 out
    gemm_mma_kernel<<<(ROWS / 128) * (VOC_PAD / 128), 256, TC_SMEM>>>(
        A2h, A2l, B2h, B2l, cls_b2, (float*)d_out, nullptr, nullptr,
        CLS_H, CLS_H, CLS_H, VOC_PAD / 128, VOC, VOC, 1);

    #undef RUN_MHA
}